// round 9
// baseline (speedup 1.0000x reference)
#include <cuda_runtime.h>
#include <math.h>

#define T_STEPS 512
#define BATCH   128
#define HID     512
#define GATES   1536
#define MROWS   (T_STEPS*BATCH)

__device__ float g_xW[(size_t)MROWS * GATES];   // 402 MB scratch
__device__ int          g_cnt4[4 * 32];          // per-row-group barrier state
__device__ volatile int g_sense4[4 * 32];

typedef unsigned long long ull;

__device__ __forceinline__ ull packf2(float lo, float hi) {
    ull r; asm("mov.b64 %0, {%1, %2};" : "=l"(r) : "f"(lo), "f"(hi)); return r;
}
__device__ __forceinline__ void unpackf2(ull v, float& lo, float& hi) {
    asm("mov.b64 {%0, %1}, %2;" : "=f"(lo), "=f"(hi) : "l"(v));
}
__device__ __forceinline__ void fma2(ull& acc, ull a, ull b) {
    asm("fma.rn.f32x2 %0, %1, %2, %0;" : "+l"(acc) : "l"(a), "l"(b));
}
__device__ __forceinline__ float sigm(float x)  { return 1.0f / (1.0f + __expf(-x)); }
__device__ __forceinline__ float tanhx(float x) { return 1.0f - 2.0f / (__expf(2.0f * x) + 1.0f); }

// ============================ Phase 1: xW GEMM =============================
__global__ __launch_bounds__(256, 2)
void xw_gemm(const float* __restrict__ A, const float* __restrict__ B,
             const float* __restrict__ bi)
{
    __shared__ __align__(16) float As[8][132];
    __shared__ __align__(16) float Bs[8][128];
    const int tid = threadIdx.x;
    const int mb = blockIdx.y * 128, nb = blockIdx.x * 128;
    const int arow = tid >> 1, ak = (tid & 1) * 4;
    const int brow = tid >> 5, bcol = (tid & 31) * 4;
    const int ty8 = (tid >> 4) * 8, tx8 = (tid & 15) * 8;

    ull acc[32];
#pragma unroll
    for (int i = 0; i < 32; i++) acc[i] = 0ull;

    const float* Ap = A + (size_t)(mb + arow) * HID + ak;
    const float* Bp = B + (size_t)brow * GATES + nb + bcol;

    for (int kt = 0; kt < 64; kt++) {
        float4 ra = *(const float4*)(Ap + kt * 8);
        float4 rb = *(const float4*)(Bp + (size_t)kt * 8 * GATES);
        As[ak + 0][arow] = ra.x; As[ak + 1][arow] = ra.y;
        As[ak + 2][arow] = ra.z; As[ak + 3][arow] = ra.w;
        *(float4*)&Bs[brow][bcol] = rb;
        __syncthreads();
#pragma unroll
        for (int kk = 0; kk < 8; kk++) {
            float4 a0 = *(const float4*)&As[kk][ty8];
            float4 a1 = *(const float4*)&As[kk][ty8 + 4];
            ulonglong2 b0 = *(const ulonglong2*)&Bs[kk][tx8];
            ulonglong2 b1 = *(const ulonglong2*)&Bs[kk][tx8 + 4];
            float ar[8] = {a0.x, a0.y, a0.z, a0.w, a1.x, a1.y, a1.z, a1.w};
#pragma unroll
            for (int i = 0; i < 8; i++) {
                ull av = packf2(ar[i], ar[i]);
                fma2(acc[i*4+0], av, b0.x); fma2(acc[i*4+1], av, b0.y);
                fma2(acc[i*4+2], av, b1.x); fma2(acc[i*4+3], av, b1.y);
            }
        }
        __syncthreads();
    }
    float4 c0 = *(const float4*)&bi[nb + tx8];
    float4 c1 = *(const float4*)&bi[nb + tx8 + 4];
#pragma unroll
    for (int i = 0; i < 8; i++) {
        float4 o0, o1;
        unpackf2(acc[i*4+0], o0.x, o0.y); unpackf2(acc[i*4+1], o0.z, o0.w);
        unpackf2(acc[i*4+2], o1.x, o1.y); unpackf2(acc[i*4+3], o1.z, o1.w);
        o0.x += c0.x; o0.y += c0.y; o0.z += c0.z; o0.w += c0.w;
        o1.x += c1.x; o1.y += c1.y; o1.z += c1.z; o1.w += c1.w;
        size_t off = (size_t)(mb + ty8 + i) * GATES + nb + tx8;
        *(float4*)&g_xW[off] = o0; *(float4*)&g_xW[off + 4] = o1;
    }
}

// ============================ Phase 2: GRU scan ============================
// Block = 32 batch rows x 16 hidden units, 256 threads: thread = (row, cu),
// row = tid>>3, cu = tid&7, units u0 = j0g + 2*cu (+1).
//   ws_rz[k*32 + cu*4]  : {Wr[u0], Wr[u0+1], Wz[u0], Wz[u0+1]}
//   ws_n [k2*32 + cu*4] : n-weights for two consecutive k packed per 16B
//   hsm[row*516 + k]    : h_prev, read as float4 per 4 k
#define HSTR  516
#define F_RZ  (HID * 32)          // 16384 floats
#define F_N   (HID * 16)          // 8192 floats
#define F_H   (32 * HSTR)         // 16512 floats
#define SCAN_SMEM ((F_RZ + F_N + F_H) * 4)   // 164,352 B

__device__ __forceinline__ void groupbar(int rc) {
    __threadfence();
    __syncthreads();
    if (threadIdx.x == 0) {
        int* cnt = &g_cnt4[rc * 32];
        volatile int* sns = &g_sense4[rc * 32];
        int s = *sns;
        if (atomicAdd(cnt, 1) == 31) {
            *cnt = 0;
            __threadfence();
            *sns = s ^ 1;
        } else {
            while (*sns == s) { __nanosleep(32); }
        }
    }
    __syncthreads();
}

__global__ __launch_bounds__(256, 1)
void gru_scan(const unsigned int* __restrict__ resets,
              const float* __restrict__ Wh,
              const float* __restrict__ bhn,
              float* __restrict__ out)
{
    extern __shared__ __align__(16) float sm[];
    float* ws_rz = sm;                  // [512][32]
    float* ws_n  = sm + F_RZ;           // [256][32]
    float* hsm   = sm + F_RZ + F_N;     // [32][516]
    __shared__ unsigned int rfl[32];

    const int bx = blockIdx.x;
    const int rc = bx & 3, jc = bx >> 2;
    const int r0 = rc * 32, j0g = jc * 16;
    const int tid = threadIdx.x;
    const int row = tid >> 3, cu = tid & 7;
    const int u0 = j0g + 2 * cu;
    const int bglob = r0 + row;

    // ---- one-time: repack this block's Wh slice ----
    for (int idx = tid; idx < HID * 8; idx += 256) {
        int k = idx >> 3, c = idx & 7;
        int uu = j0g + 2 * c;
        const float* wk = Wh + (size_t)k * GATES;
        float* drz = &ws_rz[k * 32 + c * 4];
        drz[0] = wk[uu];           drz[1] = wk[uu + 1];
        drz[2] = wk[HID + uu];     drz[3] = wk[HID + uu + 1];
        ws_n[(k >> 1) * 32 + c * 4 + (k & 1) * 2 + 0] = wk[2 * HID + uu];
        ws_n[(k >> 1) * 32 + c * 4 + (k & 1) * 2 + 1] = wk[2 * HID + uu + 1];
    }
    const float2 bh = *(const float2*)&bhn[u0];
    if (tid < 32) rfl[tid] = 1u;        // t=0 behaves as reset
    __syncthreads();

    // prefetch x gates for t=0
    const float* x0 = g_xW + (size_t)bglob * GATES;
    float2 xr = *(const float2*)(x0 + u0);
    float2 xz = *(const float2*)(x0 + HID + u0);
    float2 xn = *(const float2*)(x0 + 2 * HID + u0);

    for (int t = 0; t < T_STEPS; t++) {
        // ---- stage h_prev into smem (coalesced, reset-masked) ----
        if (t == 0) {
            float4 z4 = make_float4(0.f, 0.f, 0.f, 0.f);
#pragma unroll
            for (int i = 0; i < 16; i++) {
                int j = i * 256 + tid;
                *(float4*)&hsm[(j >> 7) * HSTR + (j & 127) * 4] = z4;
            }
        } else {
            const float* hp = out + (size_t)(t - 1) * (BATCH * HID) + (size_t)r0 * HID;
#pragma unroll
            for (int i = 0; i < 16; i++) {
                int j = i * 256 + tid;
                float4 v = *(const float4*)(hp + (size_t)j * 4);
                if (rfl[j >> 7]) v = make_float4(0.f, 0.f, 0.f, 0.f);
                *(float4*)&hsm[(j >> 7) * HSTR + (j & 127) * 4] = v;
            }
        }
        __syncthreads();

        // ---- prefetch next step's x gates + reset flags ----
        float2 nxr = xr, nxz = xz, nxn = xn;
        if (t + 1 < T_STEPS) {
            const float* nx = g_xW + (size_t)((t + 1) * BATCH + bglob) * GATES;
            nxr = *(const float2*)(nx + u0);
            nxz = *(const float2*)(nx + HID + u0);
            nxn = *(const float2*)(nx + 2 * HID + u0);
            if (tid < 32) rfl[tid] = resets[(t + 1) * BATCH + r0 + tid];
        }

        // ---- recurrent GEMM: software-pipelined (loads lead FMAs by 1 iter)
        ull accr = 0ull, accz = 0ull, accn = 0ull;
        const float* hr_ = &hsm[row * HSTR];
        const float* prz = ws_rz + cu * 4;
        const float* pn  = ws_n  + cu * 4;

        float4 h4       = *(const float4*)(hr_);
        ulonglong2 rz0  = *(const ulonglong2*)(prz);
        ulonglong2 rz1  = *(const ulonglong2*)(prz + 32);
        ulonglong2 rz2  = *(const ulonglong2*)(prz + 64);
        ulonglong2 rz3  = *(const ulonglong2*)(prz + 96);
        ulonglong2 n01  = *(const ulonglong2*)(pn);
        ulonglong2 n23  = *(const ulonglong2*)(pn + 32);

#pragma unroll 2
        for (int k4 = 0; k4 < 128; k4++) {
            // prefetch k4+1 (last iter over-reads adjacent smem; values unused)
            const float* nrz = prz + (k4 + 1) * 128;
            const float* nn  = pn  + (k4 + 1) * 64;
            float4 h4n       = *(const float4*)(hr_ + (k4 + 1) * 4);
            ulonglong2 rz0n  = *(const ulonglong2*)(nrz);
            ulonglong2 rz1n  = *(const ulonglong2*)(nrz + 32);
            ulonglong2 rz2n  = *(const ulonglong2*)(nrz + 64);
            ulonglong2 rz3n  = *(const ulonglong2*)(nrz + 96);
            ulonglong2 n01n  = *(const ulonglong2*)(nn);
            ulonglong2 n23n  = *(const ulonglong2*)(nn + 32);

            ull av;
            av = packf2(h4.x, h4.x);
            fma2(accr, av, rz0.x); fma2(accz, av, rz0.y); fma2(accn, av, n01.x);
            av = packf2(h4.y, h4.y);
            fma2(accr, av, rz1.x); fma2(accz, av, rz1.y); fma2(accn, av, n01.y);
            av = packf2(h4.z, h4.z);
            fma2(accr, av, rz2.x); fma2(accz, av, rz2.y); fma2(accn, av, n23.x);
            av = packf2(h4.w, h4.w);
            fma2(accr, av, rz3.x); fma2(accz, av, rz3.y); fma2(accn, av, n23.y);

            h4 = h4n;
            rz0 = rz0n; rz1 = rz1n; rz2 = rz2n; rz3 = rz3n;
            n01 = n01n; n23 = n23n;
        }

        float sr0, sr1, sz0, sz1, sn0, sn1;
        unpackf2(accr, sr0, sr1); unpackf2(accz, sz0, sz1); unpackf2(accn, sn0, sn1);

        float2 hpv = *(const float2*)(hr_ + u0);
        float r0g = sigm(xr.x + sr0), r1g = sigm(xr.y + sr1);
        float z0g = sigm(xz.x + sz0), z1g = sigm(xz.y + sz1);
        float n0g = tanhx(xn.x + r0g * (sn0 + bh.x));
        float n1g = tanhx(xn.y + r1g * (sn1 + bh.y));
        float2 hnew;
        hnew.x = (1.0f - z0g) * n0g + z0g * hpv.x;
        hnew.y = (1.0f - z1g) * n1g + z1g * hpv.y;

        *(float2*)(out + ((size_t)t * BATCH + bglob) * HID + u0) = hnew;

        xr = nxr; xz = nxz; xn = nxn;

        groupbar(rc);
    }
}

// ================================ Launch ===================================
extern "C" void kernel_launch(void* const* d_in, const int* in_sizes, int n_in,
                              void* d_out, int out_size)
{
    const float*        ins    = (const float*)d_in[0];
    const unsigned int* resets = (const unsigned int*)d_in[1];
    const float*        Wi     = (const float*)d_in[2];
    const float*        bi     = (const float*)d_in[3];
    const float*        Wh     = (const float*)d_in[4];
    const float*        bhn    = (const float*)d_in[5];
    float*              out    = (float*)d_out;

    dim3 g1(GATES / 128, MROWS / 128);
    xw_gemm<<<g1, 256>>>(ins, Wi, bi);

    cudaFuncSetAttribute(gru_scan, cudaFuncAttributeMaxDynamicSharedMemorySize, SCAN_SMEM);
    gru_scan<<<128, 256, SCAN_SMEM>>>(resets, Wh, bhn, out);
}

// round 10
// speedup vs baseline: 1.6370x; 1.6370x over previous
#include <cuda_runtime.h>
#include <math.h>

#define T_STEPS 512
#define BATCH   128
#define HID     512
#define GATES   1536
#define MROWS   (T_STEPS*BATCH)

__device__ float g_xW[(size_t)MROWS * GATES];   // 402 MB scratch
__device__ int          g_cnt4[4 * 32];          // per-row-group barrier state
__device__ volatile int g_sense4[4 * 32];

typedef unsigned long long ull;

__device__ __forceinline__ ull packf2(float lo, float hi) {
    ull r; asm("mov.b64 %0, {%1, %2};" : "=l"(r) : "f"(lo), "f"(hi)); return r;
}
__device__ __forceinline__ void unpackf2(ull v, float& lo, float& hi) {
    asm("mov.b64 {%0, %1}, %2;" : "=f"(lo), "=f"(hi) : "l"(v));
}
__device__ __forceinline__ void fma2(ull& acc, ull a, ull b) {
    asm("fma.rn.f32x2 %0, %1, %2, %0;" : "+l"(acc) : "l"(a), "l"(b));
}
__device__ __forceinline__ void addf2(ull& a, ull b) {
    asm("add.rn.f32x2 %0, %0, %1;" : "+l"(a) : "l"(b));
}
__device__ __forceinline__ float sigm(float x)  { return 1.0f / (1.0f + __expf(-x)); }
__device__ __forceinline__ float tanhx(float x) { return 1.0f - 2.0f / (__expf(2.0f * x) + 1.0f); }

// ============================ Phase 1: xW GEMM =============================
__global__ __launch_bounds__(256, 2)
void xw_gemm(const float* __restrict__ A, const float* __restrict__ B,
             const float* __restrict__ bi)
{
    __shared__ __align__(16) float As[8][132];
    __shared__ __align__(16) float Bs[8][128];
    const int tid = threadIdx.x;
    const int mb = blockIdx.y * 128, nb = blockIdx.x * 128;
    const int arow = tid >> 1, ak = (tid & 1) * 4;
    const int brow = tid >> 5, bcol = (tid & 31) * 4;
    const int ty8 = (tid >> 4) * 8, tx8 = (tid & 15) * 8;

    ull acc[32];
#pragma unroll
    for (int i = 0; i < 32; i++) acc[i] = 0ull;

    const float* Ap = A + (size_t)(mb + arow) * HID + ak;
    const float* Bp = B + (size_t)brow * GATES + nb + bcol;

    for (int kt = 0; kt < 64; kt++) {
        float4 ra = *(const float4*)(Ap + kt * 8);
        float4 rb = *(const float4*)(Bp + (size_t)kt * 8 * GATES);
        As[ak + 0][arow] = ra.x; As[ak + 1][arow] = ra.y;
        As[ak + 2][arow] = ra.z; As[ak + 3][arow] = ra.w;
        *(float4*)&Bs[brow][bcol] = rb;
        __syncthreads();
#pragma unroll
        for (int kk = 0; kk < 8; kk++) {
            float4 a0 = *(const float4*)&As[kk][ty8];
            float4 a1 = *(const float4*)&As[kk][ty8 + 4];
            ulonglong2 b0 = *(const ulonglong2*)&Bs[kk][tx8];
            ulonglong2 b1 = *(const ulonglong2*)&Bs[kk][tx8 + 4];
            float ar[8] = {a0.x, a0.y, a0.z, a0.w, a1.x, a1.y, a1.z, a1.w};
#pragma unroll
            for (int i = 0; i < 8; i++) {
                ull av = packf2(ar[i], ar[i]);
                fma2(acc[i*4+0], av, b0.x); fma2(acc[i*4+1], av, b0.y);
                fma2(acc[i*4+2], av, b1.x); fma2(acc[i*4+3], av, b1.y);
            }
        }
        __syncthreads();
    }
    float4 c0 = *(const float4*)&bi[nb + tx8];
    float4 c1 = *(const float4*)&bi[nb + tx8 + 4];
#pragma unroll
    for (int i = 0; i < 8; i++) {
        float4 o0, o1;
        unpackf2(acc[i*4+0], o0.x, o0.y); unpackf2(acc[i*4+1], o0.z, o0.w);
        unpackf2(acc[i*4+2], o1.x, o1.y); unpackf2(acc[i*4+3], o1.z, o1.w);
        o0.x += c0.x; o0.y += c0.y; o0.z += c0.z; o0.w += c0.w;
        o1.x += c1.x; o1.y += c1.y; o1.z += c1.z; o1.w += c1.w;
        size_t off = (size_t)(mb + ty8 + i) * GATES + nb + tx8;
        *(float4*)&g_xW[off] = o0; *(float4*)&g_xW[off + 4] = o1;
    }
}

// ============================ Phase 2: GRU scan ============================
// Block = 32 batch rows x 16 hidden units, 256 threads.
// k-loop role:   ks = tid>>6 (k-split 4), rq = (tid>>3)&7 (4 rows), cu = tid&7
//                (2 units). Each thread: 4 rows x 2 units x 3 gates over 128 k.
// epilogue role: row = tid>>3, cu = tid&7 (as R8), after 4-way smem reduction.
//   ws_rz[k*32 + cu*4]  : {Wr[u0], Wr[u0+1], Wz[u0], Wz[u0+1]}
//   ws_n [k2*32 + cu*4] : n-weights for two consecutive k packed per 16B
//   hsm[row*516 + k]    : h_prev (row-major), read as float4 per 4 k
//   red[t*13 + r*3+g]   : partial sums (ull), stride 13 to dodge conflicts
#define HSTR  516
#define F_RZ  (HID * 32)          // 16384 floats
#define F_N   (HID * 16)          // 8192 floats
#define F_H   (32 * HSTR)         // 16512 floats
#define RED_OFF (F_RZ + F_N + F_H)            // float index of red base
#define SCAN_SMEM ((RED_OFF) * 4 + 256 * 13 * 8)   // 164,352 + 26,624 = 190,976 B

__device__ __forceinline__ void groupbar(int rc) {
    __threadfence();
    __syncthreads();
    if (threadIdx.x == 0) {
        int* cnt = &g_cnt4[rc * 32];
        volatile int* sns = &g_sense4[rc * 32];
        int s = *sns;
        if (atomicAdd(cnt, 1) == 31) {
            *cnt = 0;
            __threadfence();
            *sns = s ^ 1;
        } else {
            while (*sns == s) { __nanosleep(32); }
        }
    }
    __syncthreads();
}

__global__ __launch_bounds__(256, 1)
void gru_scan(const unsigned int* __restrict__ resets,
              const float* __restrict__ Wh,
              const float* __restrict__ bhn,
              float* __restrict__ out)
{
    extern __shared__ __align__(16) float sm[];
    float* ws_rz = sm;                  // [512][32]
    float* ws_n  = sm + F_RZ;           // [256][32]
    float* hsm   = sm + F_RZ + F_N;     // [32][516]
    ull*   red   = (ull*)(sm + RED_OFF);// [256][13]
    __shared__ unsigned int rfl[32];

    const int bx = blockIdx.x;
    const int rc = bx & 3, jc = bx >> 2;
    const int r0 = rc * 32, j0g = jc * 16;
    const int tid = threadIdx.x;
    // k-loop role
    const int ks = tid >> 6;            // 0..3
    const int rq = (tid >> 3) & 7;      // 0..7 (rows rq*4 .. rq*4+3)
    const int cu = tid & 7;             // 0..7 (units 2cu, 2cu+1 local)
    // epilogue role
    const int erow = tid >> 3;          // 0..31
    const int u0 = j0g + 2 * cu;
    const int bglob = r0 + erow;

    // ---- one-time: repack this block's Wh slice (as R8) ----
    for (int idx = tid; idx < HID * 8; idx += 256) {
        int k = idx >> 3, c = idx & 7;
        int uu = j0g + 2 * c;
        const float* wk = Wh + (size_t)k * GATES;
        float* drz = &ws_rz[k * 32 + c * 4];
        drz[0] = wk[uu];           drz[1] = wk[uu + 1];
        drz[2] = wk[HID + uu];     drz[3] = wk[HID + uu + 1];
        ws_n[(k >> 1) * 32 + c * 4 + (k & 1) * 2 + 0] = wk[2 * HID + uu];
        ws_n[(k >> 1) * 32 + c * 4 + (k & 1) * 2 + 1] = wk[2 * HID + uu + 1];
    }
    const float2 bh = *(const float2*)&bhn[u0];
    if (tid < 32) rfl[tid] = 1u;        // t=0 behaves as reset
    __syncthreads();

    // prefetch x gates for t=0 (epilogue role)
    const float* x0 = g_xW + (size_t)bglob * GATES;
    float2 xr = *(const float2*)(x0 + u0);
    float2 xz = *(const float2*)(x0 + HID + u0);
    float2 xn = *(const float2*)(x0 + 2 * HID + u0);

    for (int t = 0; t < T_STEPS; t++) {
        // ---- stage h_prev into smem (coalesced, reset-masked; as R8) ----
        if (t == 0) {
            float4 z4 = make_float4(0.f, 0.f, 0.f, 0.f);
#pragma unroll
            for (int i = 0; i < 16; i++) {
                int j = i * 256 + tid;
                *(float4*)&hsm[(j >> 7) * HSTR + (j & 127) * 4] = z4;
            }
        } else {
            const float* hp = out + (size_t)(t - 1) * (BATCH * HID) + (size_t)r0 * HID;
#pragma unroll
            for (int i = 0; i < 16; i++) {
                int j = i * 256 + tid;
                float4 v = *(const float4*)(hp + (size_t)j * 4);
                if (rfl[j >> 7]) v = make_float4(0.f, 0.f, 0.f, 0.f);
                *(float4*)&hsm[(j >> 7) * HSTR + (j & 127) * 4] = v;
            }
        }
        __syncthreads();

        // ---- prefetch next step's x gates + reset flags ----
        float2 nxr = xr, nxz = xz, nxn = xn;
        if (t + 1 < T_STEPS) {
            const float* nx = g_xW + (size_t)((t + 1) * BATCH + bglob) * GATES;
            nxr = *(const float2*)(nx + u0);
            nxz = *(const float2*)(nx + HID + u0);
            nxn = *(const float2*)(nx + 2 * HID + u0);
            if (tid < 32) rfl[tid] = resets[(t + 1) * BATCH + r0 + tid];
        }

        // ---- recurrent GEMM: 4 rows x 2 units x 3 gates, k in [128ks,128ks+128)
        ull accr[4] = {0ull,0ull,0ull,0ull};
        ull accz[4] = {0ull,0ull,0ull,0ull};
        ull accn[4] = {0ull,0ull,0ull,0ull};
        {
            const float* h0 = &hsm[(rq * 4 + 0) * HSTR];
            const float* h1 = &hsm[(rq * 4 + 1) * HSTR];
            const float* h2 = &hsm[(rq * 4 + 2) * HSTR];
            const float* h3 = &hsm[(rq * 4 + 3) * HSTR];
            const float* prz = ws_rz + cu * 4;
            const float* pn  = ws_n  + cu * 4;
#pragma unroll 2
            for (int q = ks * 32; q < ks * 32 + 32; q++) {   // q = k4 index
                float4 a0 = *(const float4*)(h0 + q * 4);
                float4 a1 = *(const float4*)(h1 + q * 4);
                float4 a2 = *(const float4*)(h2 + q * 4);
                float4 a3 = *(const float4*)(h3 + q * 4);
                const float* wrz = prz + (q * 4) * 32;
                ulonglong2 rz0 = *(const ulonglong2*)(wrz);
                ulonglong2 rz1 = *(const ulonglong2*)(wrz + 32);
                ulonglong2 rz2 = *(const ulonglong2*)(wrz + 64);
                ulonglong2 rz3 = *(const ulonglong2*)(wrz + 96);
                const float* wn = pn + (q * 2) * 32;
                ulonglong2 n01 = *(const ulonglong2*)(wn);
                ulonglong2 n23 = *(const ulonglong2*)(wn + 32);

                ull av;
                av = packf2(a0.x, a0.x); fma2(accr[0], av, rz0.x); fma2(accz[0], av, rz0.y); fma2(accn[0], av, n01.x);
                av = packf2(a0.y, a0.y); fma2(accr[0], av, rz1.x); fma2(accz[0], av, rz1.y); fma2(accn[0], av, n01.y);
                av = packf2(a0.z, a0.z); fma2(accr[0], av, rz2.x); fma2(accz[0], av, rz2.y); fma2(accn[0], av, n23.x);
                av = packf2(a0.w, a0.w); fma2(accr[0], av, rz3.x); fma2(accz[0], av, rz3.y); fma2(accn[0], av, n23.y);

                av = packf2(a1.x, a1.x); fma2(accr[1], av, rz0.x); fma2(accz[1], av, rz0.y); fma2(accn[1], av, n01.x);
                av = packf2(a1.y, a1.y); fma2(accr[1], av, rz1.x); fma2(accz[1], av, rz1.y); fma2(accn[1], av, n01.y);
                av = packf2(a1.z, a1.z); fma2(accr[1], av, rz2.x); fma2(accz[1], av, rz2.y); fma2(accn[1], av, n23.x);
                av = packf2(a1.w, a1.w); fma2(accr[1], av, rz3.x); fma2(accz[1], av, rz3.y); fma2(accn[1], av, n23.y);

                av = packf2(a2.x, a2.x); fma2(accr[2], av, rz0.x); fma2(accz[2], av, rz0.y); fma2(accn[2], av, n01.x);
                av = packf2(a2.y, a2.y); fma2(accr[2], av, rz1.x); fma2(accz[2], av, rz1.y); fma2(accn[2], av, n01.y);
                av = packf2(a2.z, a2.z); fma2(accr[2], av, rz2.x); fma2(accz[2], av, rz2.y); fma2(accn[2], av, n23.x);
                av = packf2(a2.w, a2.w); fma2(accr[2], av, rz3.x); fma2(accz[2], av, rz3.y); fma2(accn[2], av, n23.y);

                av = packf2(a3.x, a3.x); fma2(accr[3], av, rz0.x); fma2(accz[3], av, rz0.y); fma2(accn[3], av, n01.x);
                av = packf2(a3.y, a3.y); fma2(accr[3], av, rz1.x); fma2(accz[3], av, rz1.y); fma2(accn[3], av, n01.y);
                av = packf2(a3.z, a3.z); fma2(accr[3], av, rz2.x); fma2(accz[3], av, rz2.y); fma2(accn[3], av, n23.x);
                av = packf2(a3.w, a3.w); fma2(accr[3], av, rz3.x); fma2(accz[3], av, rz3.y); fma2(accn[3], av, n23.y);
            }
        }

        // ---- store partials, reduce 4-way, epilogue in (erow, cu) role ----
        {
            ull* rp = red + tid * 13;
#pragma unroll
            for (int r = 0; r < 4; r++) {
                rp[r * 3 + 0] = accr[r];
                rp[r * 3 + 1] = accz[r];
                rp[r * 3 + 2] = accn[r];
            }
        }
        __syncthreads();

        ull sR = 0ull, sZ = 0ull, sN = 0ull;
        {
            int erq = erow >> 2, err = erow & 3;
#pragma unroll
            for (int s = 0; s < 4; s++) {
                const ull* rp = red + (size_t)(((s * 8 + erq) * 8 + cu)) * 13 + err * 3;
                addf2(sR, rp[0]); addf2(sZ, rp[1]); addf2(sN, rp[2]);
            }
        }

        float sr0, sr1, sz0, sz1, sn0, sn1;
        unpackf2(sR, sr0, sr1); unpackf2(sZ, sz0, sz1); unpackf2(sN, sn0, sn1);

        float2 hpv = *(const float2*)(&hsm[erow * HSTR] + u0);
        float r0g = sigm(xr.x + sr0), r1g = sigm(xr.y + sr1);
        float z0g = sigm(xz.x + sz0), z1g = sigm(xz.y + sz1);
        float n0g = tanhx(xn.x + r0g * (sn0 + bh.x));
        float n1g = tanhx(xn.y + r1g * (sn1 + bh.y));
        float2 hnew;
        hnew.x = (1.0f - z0g) * n0g + z0g * hpv.x;
        hnew.y = (1.0f - z1g) * n1g + z1g * hpv.y;

        *(float2*)(out + ((size_t)t * BATCH + bglob) * HID + u0) = hnew;

        xr = nxr; xz = nxz; xn = nxn;

        groupbar(rc);
    }
}

// ================================ Launch ===================================
extern "C" void kernel_launch(void* const* d_in, const int* in_sizes, int n_in,
                              void* d_out, int out_size)
{
    const float*        ins    = (const float*)d_in[0];
    const unsigned int* resets = (const unsigned int*)d_in[1];
    const float*        Wi     = (const float*)d_in[2];
    const float*        bi     = (const float*)d_in[3];
    const float*        Wh     = (const float*)d_in[4];
    const float*        bhn    = (const float*)d_in[5];
    float*              out    = (float*)d_out;

    dim3 g1(GATES / 128, MROWS / 128);
    xw_gemm<<<g1, 256>>>(ins, Wi, bi);

    cudaFuncSetAttribute(gru_scan, cudaFuncAttributeMaxDynamicSharedMemorySize, SCAN_SMEM);
    gru_scan<<<128, 256, SCAN_SMEM>>>(resets, Wh, bhn, out);
}